// round 3
// baseline (speedup 1.0000x reference)
#include <cuda_runtime.h>

// AverageGridEncoder: scatter-mean of z over nearest grid cell, + latents.
// Counting-sort + gather. R3: revert __ldcs (latency regression), break the
// perm->z pointer chase via lane-parallel perm prefetch + shfl broadcast,
// unroll-4 z loads (MLP 4).

#define P0 128
#define P1 128
#define NCELLS (P0 * P1)      // 16384
#define EMBED 128
#define MAXB 4
#define MAXN 100000

// Scratch (allocation-free rule: __device__ globals, zero-initialized at load;
// gather_kernel restores g_count to all-zero each call -> deterministic).
__device__ int g_count[MAXB * NCELLS];
__device__ int g_offset[MAXB * NCELLS];
__device__ int g_cellrank[MAXB * MAXN];   // cell (14b) | rank<<14 (17b)
__device__ int g_perm[MAXB * MAXN];

// Per-point cell index + histogram. The atomicAdd return value is this
// point's rank within its cell -> pack it so scatter needs no atomics.
// step = 1/127 f32, IEEE divide + rintf (half-even) to match XLA round().
__global__ void hist_kernel(const float* __restrict__ x, int BN, int N) {
    int i = blockIdx.x * blockDim.x + threadIdx.x;
    if (i >= BN) return;
    float2 p = reinterpret_cast<const float2*>(x)[i];
    const float step = 1.0f / 127.0f;
    int i0 = (int)rintf(p.x / step);
    int i1 = (int)rintf(p.y / step);
    i0 = min(max(i0, 0), P0 - 1);
    i1 = min(max(i1, 0), P1 - 1);
    int cell = i0 * P1 + i1;
    int b = i / N;
    int rank = atomicAdd(&g_count[b * NCELLS + cell], 1);
    g_cellrank[i] = cell | (rank << 14);
}

// One block per batch: exclusive prefix sum over 16384 counts (int4 loads).
__global__ void scan_kernel() {
    __shared__ int s[1024];
    int b = blockIdx.x;
    int t = threadIdx.x;
    int base = b * NCELLS;
    const int4* cnt4 = reinterpret_cast<const int4*>(g_count + base);
    int4* off4 = reinterpret_cast<int4*>(g_offset + base);
    int4 v[4];
    int sum = 0;
#pragma unroll
    for (int k = 0; k < 4; k++) {
        v[k] = cnt4[t * 4 + k];
        sum += v[k].x + v[k].y + v[k].z + v[k].w;
    }
    s[t] = sum;
    __syncthreads();
    for (int off = 1; off < 1024; off <<= 1) {
        int u = (t >= off) ? s[t - off] : 0;
        __syncthreads();
        s[t] += u;
        __syncthreads();
    }
    int run = s[t] - sum;  // exclusive prefix of this thread's chunk
#pragma unroll
    for (int k = 0; k < 4; k++) {
        int4 o;
        o.x = run;            run += v[k].x;
        o.y = run;            run += v[k].y;
        o.z = run;            run += v[k].z;
        o.w = run;            run += v[k].w;
        off4[t * 4 + k] = o;
    }
}

// Atomic-free scatter: slot = start[cell] + rank (rank from hist).
__global__ void scatter_kernel(int BN, int N) {
    int i = blockIdx.x * blockDim.x + threadIdx.x;
    if (i >= BN) return;
    int b = i / N;
    int n = i - b * N;
    unsigned v = (unsigned)g_cellrank[i];
    int cell = (int)(v & 16383u);
    int rank = (int)(v >> 14);
    int start = g_offset[b * NCELLS + cell];   // L2-resident (256KB)
    g_perm[b * N + start + rank] = n;
}

// One warp per (batch, cell). Each lane owns 4 embed dims (float4).
// Perm indices are prefetched lane-parallel (one coalesced load per warp)
// and broadcast via shfl -> z loads have no dependent chase, MLP=4.
// Also resets g_count to zero for the next call.
__global__ void gather_kernel(const float* __restrict__ z,
                              const float* __restrict__ latents,
                              float* __restrict__ out_x,
                              float* __restrict__ out_z,
                              int B, int N) {
    int gwarp = (blockIdx.x * blockDim.x + threadIdx.x) >> 5;
    int lane = threadIdx.x & 31;
    int total = B * NCELLS;
    if (gwarp >= total) return;

    int b = gwarp / NCELLS;
    int cell = gwarp - b * NCELLS;
    int idx = gwarp;  // b*NCELLS + cell

    int start = g_offset[idx];
    int cnt = g_count[idx];
    if (lane == 0) g_count[idx] = 0;           // self-reset for next call

    const float4* zb = reinterpret_cast<const float4*>(z) +
                       (size_t)b * N * (EMBED / 4);
    const int* perm = g_perm + b * N + start;

    // Lane-parallel prefetch of up to 32 point indices (one coalesced LDG).
    int pk = (lane < cnt) ? perm[lane] : 0;

    float4 a0 = make_float4(0.f, 0.f, 0.f, 0.f);
    float4 a1 = make_float4(0.f, 0.f, 0.f, 0.f);
    float4 a2 = make_float4(0.f, 0.f, 0.f, 0.f);
    float4 a3 = make_float4(0.f, 0.f, 0.f, 0.f);

    int kmax = min(cnt, 32);
    int k = 0;
    for (; k + 3 < kmax; k += 4) {
        int p0 = __shfl_sync(0xffffffffu, pk, k);
        int p1 = __shfl_sync(0xffffffffu, pk, k + 1);
        int p2 = __shfl_sync(0xffffffffu, pk, k + 2);
        int p3 = __shfl_sync(0xffffffffu, pk, k + 3);
        float4 v0 = zb[(size_t)p0 * (EMBED / 4) + lane];
        float4 v1 = zb[(size_t)p1 * (EMBED / 4) + lane];
        float4 v2 = zb[(size_t)p2 * (EMBED / 4) + lane];
        float4 v3 = zb[(size_t)p3 * (EMBED / 4) + lane];
        a0.x += v0.x; a0.y += v0.y; a0.z += v0.z; a0.w += v0.w;
        a1.x += v1.x; a1.y += v1.y; a1.z += v1.z; a1.w += v1.w;
        a2.x += v2.x; a2.y += v2.y; a2.z += v2.z; a2.w += v2.w;
        a3.x += v3.x; a3.y += v3.y; a3.z += v3.z; a3.w += v3.w;
    }
    for (; k < kmax; k++) {
        int p0 = __shfl_sync(0xffffffffu, pk, k);
        float4 v0 = zb[(size_t)p0 * (EMBED / 4) + lane];
        a0.x += v0.x; a0.y += v0.y; a0.z += v0.z; a0.w += v0.w;
    }
    // Rare tail: cells with >32 points (uniform data makes this unlikely).
    for (; k < cnt; k++) {
        int p0 = perm[k];
        float4 v0 = zb[(size_t)p0 * (EMBED / 4) + lane];
        a0.x += v0.x; a0.y += v0.y; a0.z += v0.z; a0.w += v0.w;
    }

    a0.x += a1.x + a2.x + a3.x;
    a0.y += a1.y + a2.y + a3.y;
    a0.z += a1.z + a2.z + a3.z;
    a0.w += a1.w + a2.w + a3.w;

    float inv = (cnt > 0) ? (1.0f / (float)cnt) : 0.0f;
    float4 l = reinterpret_cast<const float4*>(latents)[cell * (EMBED / 4) + lane];
    float4 o;
    o.x = l.x + a0.x * inv;
    o.y = l.y + a0.y * inv;
    o.z = l.z + a0.z * inv;
    o.w = l.w + a0.w * inv;
    reinterpret_cast<float4*>(out_z)[(size_t)idx * (EMBED / 4) + lane] = o;

    if (lane == 0) {
        int i0 = cell / P1;
        int i1 = cell - i0 * P1;
        const float step = 1.0f / 127.0f;
        float2 g = make_float2((float)i0 * step, (float)i1 * step);
        reinterpret_cast<float2*>(out_x)[idx] = g;
    }
}

extern "C" void kernel_launch(void* const* d_in, const int* in_sizes, int n_in,
                              void* d_out, int out_size) {
    // Identify inputs by size: z is largest, x is smallest, latents in between.
    int ix = 0, iz = 0, il = 0;
    for (int i = 1; i < n_in; i++) {
        if (in_sizes[i] > in_sizes[iz]) iz = i;
        if (in_sizes[i] < in_sizes[ix]) ix = i;
    }
    for (int i = 0; i < n_in; i++)
        if (i != ix && i != iz) il = i;

    const float* x = (const float*)d_in[ix];
    const float* z = (const float*)d_in[iz];
    const float* latents = (const float*)d_in[il];

    int BN = in_sizes[ix] / 2;                        // B*N
    int B = out_size / (NCELLS * (2 + EMBED));        // per-batch out = 16384*130
    if (B < 1) B = 1;
    int N = BN / B;

    float* out_x = (float*)d_out;                     // [B,128,128,2]
    float* out_z = (float*)d_out + (size_t)B * NCELLS * 2;  // [B,128,128,128]

    int cells = B * NCELLS;
    hist_kernel<<<(BN + 255) / 256, 256>>>(x, BN, N);
    scan_kernel<<<B, 1024>>>();
    scatter_kernel<<<(BN + 255) / 256, 256>>>(BN, N);
    int threads_total = cells * 32;                   // one warp per cell
    gather_kernel<<<(threads_total + 255) / 256, 256>>>(z, latents, out_x, out_z, B, N);
}

// round 4
// speedup vs baseline: 1.7116x; 1.7116x over previous
#include <cuda_runtime.h>

// AverageGridEncoder: scatter-mean of z over nearest grid cell, + latents.
// R4: block-staged gather. 64 consecutive cells per block; offsets + the
// contiguous perm slice are cooperatively loaded to SMEM (coalesced), so
// warps' z-row bursts run back-to-back with no per-cell GMEM metadata chain.

#define P0 128
#define P1 128
#define NCELLS (P0 * P1)      // 16384
#define EMBED 128
#define MAXB 4
#define MAXN 100000
#define CPB 64                // cells per block
#define PERMBUF 1024          // smem perm slice capacity (E[len]=390, sd~20)

// Scratch (allocation-free rule: __device__ globals, zero at load; gather
// restores g_count to zero each call -> deterministic across replays).
__device__ int g_count[MAXB * NCELLS];
__device__ int g_offset[MAXB * NCELLS];
__device__ int g_cellrank[MAXB * MAXN];   // cell (14b) | rank<<14
__device__ int g_perm[MAXB * MAXN];

// Per-point cell + histogram; atomic return = rank within cell.
// 1/127 f32 step, IEEE divide + rintf (half-even) to match XLA round().
__global__ void hist_kernel(const float* __restrict__ x, int BN, int N) {
    int i = blockIdx.x * blockDim.x + threadIdx.x;
    if (i >= BN) return;
    float2 p = reinterpret_cast<const float2*>(x)[i];
    const float step = 1.0f / 127.0f;
    int i0 = (int)rintf(p.x / step);
    int i1 = (int)rintf(p.y / step);
    i0 = min(max(i0, 0), P0 - 1);
    i1 = min(max(i1, 0), P1 - 1);
    int cell = i0 * P1 + i1;
    int b = i / N;
    int rank = atomicAdd(&g_count[b * NCELLS + cell], 1);
    g_cellrank[i] = cell | (rank << 14);
}

// One block per batch: exclusive prefix sum over 16384 counts (int4).
__global__ void scan_kernel() {
    __shared__ int s[1024];
    int b = blockIdx.x;
    int t = threadIdx.x;
    int base = b * NCELLS;
    const int4* cnt4 = reinterpret_cast<const int4*>(g_count + base);
    int4* off4 = reinterpret_cast<int4*>(g_offset + base);
    int4 v[4];
    int sum = 0;
#pragma unroll
    for (int k = 0; k < 4; k++) {
        v[k] = cnt4[t * 4 + k];
        sum += v[k].x + v[k].y + v[k].z + v[k].w;
    }
    s[t] = sum;
    __syncthreads();
    for (int off = 1; off < 1024; off <<= 1) {
        int u = (t >= off) ? s[t - off] : 0;
        __syncthreads();
        s[t] += u;
        __syncthreads();
    }
    int run = s[t] - sum;
#pragma unroll
    for (int k = 0; k < 4; k++) {
        int4 o;
        o.x = run; run += v[k].x;
        o.y = run; run += v[k].y;
        o.z = run; run += v[k].z;
        o.w = run; run += v[k].w;
        off4[t * 4 + k] = o;
    }
}

// Atomic-free scatter: slot = start[cell] + rank.
__global__ void scatter_kernel(int BN, int N) {
    int i = blockIdx.x * blockDim.x + threadIdx.x;
    if (i >= BN) return;
    int b = i / N;
    int n = i - b * N;
    unsigned v = (unsigned)g_cellrank[i];
    int cell = (int)(v & 16383u);
    int rank = (int)(v >> 14);
    int start = g_offset[b * NCELLS + cell];   // L2-resident
    g_perm[b * N + start + rank] = n;
}

// Block = 64 consecutive cells of one batch (64 | 16384, never spans batches).
// Stage offsets + perm slice in SMEM, then 8 warps x 8 cells each stream z.
__global__ __launch_bounds__(256) void gather_kernel(
        const float* __restrict__ z,
        const float* __restrict__ latents,
        float* __restrict__ out_x,
        float* __restrict__ out_z,
        int B, int N) {
    __shared__ int s_perm[PERMBUF];
    __shared__ int s_off[CPB + 1];

    int t = threadIdx.x;
    int cellbase = blockIdx.x * CPB;          // global cell index
    int b = cellbase / NCELLS;

    if (t < CPB) {
        s_off[t] = g_offset[cellbase + t];
        g_count[cellbase + t] = 0;            // reset for next replay
    } else if (t == CPB) {
        int g = cellbase + CPB;
        s_off[CPB] = ((g & (NCELLS - 1)) == 0) ? N : g_offset[g];
    }
    __syncthreads();

    int slice_start = s_off[0];
    int slice_len = s_off[CPB] - slice_start;
    const int* permb = g_perm + b * N;
    bool in_smem = (slice_len <= PERMBUF);
    if (in_smem) {
        for (int i = t; i < slice_len; i += 256)
            s_perm[i] = permb[slice_start + i];
    }
    __syncthreads();

    int w = t >> 5, lane = t & 31;
    const float4* zb = reinterpret_cast<const float4*>(z) +
                       (size_t)b * N * (EMBED / 4);

#pragma unroll 1
    for (int j = 0; j < 8; j++) {
        int lc = w * 8 + j;                   // local cell 0..63
        int cs = s_off[lc] - slice_start;
        int ce = s_off[lc + 1] - slice_start;
        int cnt = ce - cs;

        float4 a0 = make_float4(0.f, 0.f, 0.f, 0.f);
        float4 a1 = make_float4(0.f, 0.f, 0.f, 0.f);
        float4 a2 = make_float4(0.f, 0.f, 0.f, 0.f);
        float4 a3 = make_float4(0.f, 0.f, 0.f, 0.f);

        int k = cs;
        if (in_smem) {
            for (; k + 3 < ce; k += 4) {
                int p0 = s_perm[k];
                int p1 = s_perm[k + 1];
                int p2 = s_perm[k + 2];
                int p3 = s_perm[k + 3];
                float4 v0 = zb[(size_t)p0 * (EMBED / 4) + lane];
                float4 v1 = zb[(size_t)p1 * (EMBED / 4) + lane];
                float4 v2 = zb[(size_t)p2 * (EMBED / 4) + lane];
                float4 v3 = zb[(size_t)p3 * (EMBED / 4) + lane];
                a0.x += v0.x; a0.y += v0.y; a0.z += v0.z; a0.w += v0.w;
                a1.x += v1.x; a1.y += v1.y; a1.z += v1.z; a1.w += v1.w;
                a2.x += v2.x; a2.y += v2.y; a2.z += v2.z; a2.w += v2.w;
                a3.x += v3.x; a3.y += v3.y; a3.z += v3.z; a3.w += v3.w;
            }
            for (; k < ce; k++) {
                int p0 = s_perm[k];
                float4 v0 = zb[(size_t)p0 * (EMBED / 4) + lane];
                a0.x += v0.x; a0.y += v0.y; a0.z += v0.z; a0.w += v0.w;
            }
        } else {
            // Pathological slice (>PERMBUF points in 64 cells): gmem path.
            for (; k < ce; k++) {
                int p0 = permb[slice_start + k];
                float4 v0 = zb[(size_t)p0 * (EMBED / 4) + lane];
                a0.x += v0.x; a0.y += v0.y; a0.z += v0.z; a0.w += v0.w;
            }
        }

        a0.x += a1.x + a2.x + a3.x;
        a0.y += a1.y + a2.y + a3.y;
        a0.z += a1.z + a2.z + a3.z;
        a0.w += a1.w + a2.w + a3.w;

        int gc = cellbase + lc;
        int cell = gc & (NCELLS - 1);
        float inv = (cnt > 0) ? (1.0f / (float)cnt) : 0.0f;
        float4 l = reinterpret_cast<const float4*>(latents)[cell * (EMBED / 4) + lane];
        float4 o;
        o.x = l.x + a0.x * inv;
        o.y = l.y + a0.y * inv;
        o.z = l.z + a0.z * inv;
        o.w = l.w + a0.w * inv;
        reinterpret_cast<float4*>(out_z)[(size_t)gc * (EMBED / 4) + lane] = o;
    }

    // x_grid: 64 cells x 2 floats, coalesced by 128 threads.
    if (t < 2 * CPB) {
        int gc = cellbase + (t >> 1);
        int cell = gc & (NCELLS - 1);
        int d = t & 1;
        int i0 = cell >> 7;
        int i1 = cell & (P1 - 1);
        const float step = 1.0f / 127.0f;
        float v = (float)(d == 0 ? i0 : i1) * step;
        out_x[(size_t)gc * 2 + d] = v;
    }
}

extern "C" void kernel_launch(void* const* d_in, const int* in_sizes, int n_in,
                              void* d_out, int out_size) {
    // Identify inputs by size: z largest, x smallest, latents remaining.
    int ix = 0, iz = 0, il = 0;
    for (int i = 1; i < n_in; i++) {
        if (in_sizes[i] > in_sizes[iz]) iz = i;
        if (in_sizes[i] < in_sizes[ix]) ix = i;
    }
    for (int i = 0; i < n_in; i++)
        if (i != ix && i != iz) il = i;

    const float* x = (const float*)d_in[ix];
    const float* z = (const float*)d_in[iz];
    const float* latents = (const float*)d_in[il];

    int BN = in_sizes[ix] / 2;                        // B*N
    int B = out_size / (NCELLS * (2 + EMBED));
    if (B < 1) B = 1;
    int N = BN / B;

    float* out_x = (float*)d_out;                     // [B,128,128,2]
    float* out_z = (float*)d_out + (size_t)B * NCELLS * 2;  // [B,128,128,128]

    int cells = B * NCELLS;
    hist_kernel<<<(BN + 255) / 256, 256>>>(x, BN, N);
    scan_kernel<<<B, 1024>>>();
    scatter_kernel<<<(BN + 255) / 256, 256>>>(BN, N);
    gather_kernel<<<cells / CPB, 256>>>(z, latents, out_x, out_z, B, N);
}

// round 5
// speedup vs baseline: 1.9484x; 1.1383x over previous
#include <cuda_runtime.h>

// AverageGridEncoder: scatter-mean of z over nearest grid cell, + latents.
// R5: flat-stream gather. Each warp owns 8 consecutive cells = one contiguous
// perm range; a single unroll-4 loop keeps 4 z-row loads in flight at all
// times, cell boundaries handled by warp-uniform flush (no per-cell drain).

#define P0 128
#define P1 128
#define NCELLS (P0 * P1)      // 16384
#define EMBED 128
#define MAXB 4
#define MAXN 100000
#define CPB 64                // cells per block
#define PERMBUF 1024          // smem perm slice capacity (E[len]=391, sd~20)

__device__ int g_count[MAXB * NCELLS];
__device__ int g_offset[MAXB * NCELLS];
__device__ int g_cellrank[MAXB * MAXN];   // cell (14b) | rank<<14
__device__ int g_perm[MAXB * MAXN];

// Per-point cell + histogram; atomic return = rank within cell.
// 1/127 f32 step, IEEE divide + rintf (half-even) to match XLA round().
__global__ void hist_kernel(const float* __restrict__ x, int BN, int N) {
    int i = blockIdx.x * blockDim.x + threadIdx.x;
    if (i >= BN) return;
    float2 p = reinterpret_cast<const float2*>(x)[i];
    const float step = 1.0f / 127.0f;
    int i0 = (int)rintf(p.x / step);
    int i1 = (int)rintf(p.y / step);
    i0 = min(max(i0, 0), P0 - 1);
    i1 = min(max(i1, 0), P1 - 1);
    int cell = i0 * P1 + i1;
    int b = i / N;
    int rank = atomicAdd(&g_count[b * NCELLS + cell], 1);
    g_cellrank[i] = cell | (rank << 14);
}

// One block per batch: exclusive prefix over 16384 counts, shuffle scan.
__global__ void scan_kernel() {
    __shared__ int warp_sums[32];
    int b = blockIdx.x;
    int t = threadIdx.x;
    int lane = t & 31, wid = t >> 5;
    int base = b * NCELLS;
    const int4* cnt4 = reinterpret_cast<const int4*>(g_count + base);
    int4* off4 = reinterpret_cast<int4*>(g_offset + base);
    int4 v[4];
    int sum = 0;
#pragma unroll
    for (int k = 0; k < 4; k++) {
        v[k] = cnt4[t * 4 + k];
        sum += v[k].x + v[k].y + v[k].z + v[k].w;
    }
    int inc = sum;                      // warp inclusive scan
#pragma unroll
    for (int d = 1; d < 32; d <<= 1) {
        int s = __shfl_up_sync(0xffffffffu, inc, d);
        if (lane >= d) inc += s;
    }
    if (lane == 31) warp_sums[wid] = inc;
    __syncthreads();
    if (wid == 0) {
        int ws = warp_sums[lane];
#pragma unroll
        for (int d = 1; d < 32; d <<= 1) {
            int s = __shfl_up_sync(0xffffffffu, ws, d);
            if (lane >= d) ws += s;
        }
        warp_sums[lane] = ws;
    }
    __syncthreads();
    int run = (wid > 0 ? warp_sums[wid - 1] : 0) + inc - sum;  // exclusive
#pragma unroll
    for (int k = 0; k < 4; k++) {
        int4 o;
        o.x = run; run += v[k].x;
        o.y = run; run += v[k].y;
        o.z = run; run += v[k].z;
        o.w = run; run += v[k].w;
        off4[t * 4 + k] = o;
    }
}

// Atomic-free scatter: slot = start[cell] + rank.
__global__ void scatter_kernel(int BN, int N) {
    int i = blockIdx.x * blockDim.x + threadIdx.x;
    if (i >= BN) return;
    int b = i / N;
    int n = i - b * N;
    unsigned v = (unsigned)g_cellrank[i];
    int cell = (int)(v & 16383u);
    int rank = (int)(v >> 14);
    int start = g_offset[b * NCELLS + cell];   // L2-resident
    g_perm[b * N + start + rank] = n;
}

// Block = 64 consecutive cells of one batch; warp = 8 cells = one contiguous
// point range. Flat unroll-4 stream with warp-uniform boundary flushes.
__global__ __launch_bounds__(256, 5) void gather_kernel(
        const float* __restrict__ z,
        const float* __restrict__ latents,
        float* __restrict__ out_x,
        float* __restrict__ out_z,
        int B, int N) {
    __shared__ int s_perm[PERMBUF];
    __shared__ int s_off[CPB + 1];

    int t = threadIdx.x;
    int cellbase = blockIdx.x * CPB;          // global cell index
    int b = cellbase / NCELLS;

    if (t <= CPB) {
        int g = cellbase + t;
        int v = (t == CPB && (g & (NCELLS - 1)) == 0) ? N : g_offset[g];
        s_off[t] = v;
        if (t < CPB) g_count[cellbase + t] = 0;   // reset for next replay
    }
    __syncthreads();

    int slice_start = s_off[0];
    int slice_len = s_off[CPB] - slice_start;
    const int* permb = g_perm + b * N + slice_start;
    bool in_smem = (slice_len <= PERMBUF);
    if (in_smem) {
        for (int i = t; i < slice_len; i += 256)
            s_perm[i] = permb[i];
    }
    __syncthreads();
    const int* psrc = in_smem ? (const int*)s_perm : permb;  // generic ptr

    int w = t >> 5, lane = t & 31;
    const float4* zb = reinterpret_cast<const float4*>(z) +
                       (size_t)b * N * (EMBED / 4);
    const float4* lat4 = reinterpret_cast<const float4*>(latents);
    float4* outz4 = reinterpret_cast<float4*>(out_z);

    int lc = w * 8;                       // local cell
    const int last = lc + 8;
    int p = s_off[lc] - slice_start;
    const int wend = s_off[last] - slice_start;
    int cstart = p;
    int nend = s_off[lc + 1] - slice_start;
    float4 acc = make_float4(0.f, 0.f, 0.f, 0.f);
    float4 lat = lat4[(size_t)((cellbase + lc) & (NCELLS - 1)) * (EMBED / 4) + lane];

    auto flush = [&]() {
        int gc = cellbase + lc;
        int cnt = nend - cstart;
        float inv = (cnt > 0) ? (1.0f / (float)cnt) : 0.0f;
        float4 o;
        o.x = lat.x + acc.x * inv;
        o.y = lat.y + acc.y * inv;
        o.z = lat.z + acc.z * inv;
        o.w = lat.w + acc.w * inv;
        outz4[(size_t)gc * (EMBED / 4) + lane] = o;
        lc++;
        cstart = nend;
        if (lc < last) {
            nend = s_off[lc + 1] - slice_start;
            lat = lat4[(size_t)((cellbase + lc) & (NCELLS - 1)) * (EMBED / 4) + lane];
        }
        acc = make_float4(0.f, 0.f, 0.f, 0.f);
    };

    while (p + 4 <= wend) {
        int i0 = psrc[p];
        int i1 = psrc[p + 1];
        int i2 = psrc[p + 2];
        int i3 = psrc[p + 3];
        float4 v0 = zb[(size_t)i0 * (EMBED / 4) + lane];
        float4 v1 = zb[(size_t)i1 * (EMBED / 4) + lane];
        float4 v2 = zb[(size_t)i2 * (EMBED / 4) + lane];
        float4 v3 = zb[(size_t)i3 * (EMBED / 4) + lane];
        while (p == nend) flush();
        acc.x += v0.x; acc.y += v0.y; acc.z += v0.z; acc.w += v0.w; p++;
        while (p == nend) flush();
        acc.x += v1.x; acc.y += v1.y; acc.z += v1.z; acc.w += v1.w; p++;
        while (p == nend) flush();
        acc.x += v2.x; acc.y += v2.y; acc.z += v2.z; acc.w += v2.w; p++;
        while (p == nend) flush();
        acc.x += v3.x; acc.y += v3.y; acc.z += v3.z; acc.w += v3.w; p++;
    }
    while (p < wend) {
        int i0 = psrc[p];
        float4 v0 = zb[(size_t)i0 * (EMBED / 4) + lane];
        while (p == nend) flush();
        acc.x += v0.x; acc.y += v0.y; acc.z += v0.z; acc.w += v0.w; p++;
    }
    while (lc < last) flush();            // trailing (possibly empty) cells

    // x_grid: 64 cells x 2 floats, coalesced by 128 threads.
    if (t < 2 * CPB) {
        int gc = cellbase + (t >> 1);
        int cell = gc & (NCELLS - 1);
        int d = t & 1;
        int i0 = cell >> 7;
        int i1 = cell & (P1 - 1);
        const float step = 1.0f / 127.0f;
        out_x[(size_t)gc * 2 + d] = (float)(d == 0 ? i0 : i1) * step;
    }
}

extern "C" void kernel_launch(void* const* d_in, const int* in_sizes, int n_in,
                              void* d_out, int out_size) {
    // Identify inputs by size: z largest, x smallest, latents remaining.
    int ix = 0, iz = 0, il = 0;
    for (int i = 1; i < n_in; i++) {
        if (in_sizes[i] > in_sizes[iz]) iz = i;
        if (in_sizes[i] < in_sizes[ix]) ix = i;
    }
    for (int i = 0; i < n_in; i++)
        if (i != ix && i != iz) il = i;

    const float* x = (const float*)d_in[ix];
    const float* z = (const float*)d_in[iz];
    const float* latents = (const float*)d_in[il];

    int BN = in_sizes[ix] / 2;                        // B*N
    int B = out_size / (NCELLS * (2 + EMBED));
    if (B < 1) B = 1;
    int N = BN / B;

    float* out_x = (float*)d_out;                     // [B,128,128,2]
    float* out_z = (float*)d_out + (size_t)B * NCELLS * 2;  // [B,128,128,128]

    int cells = B * NCELLS;
    hist_kernel<<<(BN + 255) / 256, 256>>>(x, BN, N);
    scan_kernel<<<B, 1024>>>();
    scatter_kernel<<<(BN + 255) / 256, 256>>>(BN, N);
    gather_kernel<<<cells / CPB, 256>>>(z, latents, out_x, out_z, B, N);
}